// round 3
// baseline (speedup 1.0000x reference)
#include <cuda_runtime.h>
#include <cuda_bf16.h>
#include <math.h>

// Problem shape (fixed by dataset)
#define B_    2
#define N_    50000
#define D_    128
#define E_    800000
#define ROWS_ (B_ * N_)   // 100000 rows when H viewed as [B*N, D]

// Scratch: device globals (no allocation allowed)
__device__ float g_m[(size_t)ROWS_ * D_];    // m = H @ W
__device__ float g_agg[(size_t)ROWS_ * D_];  // scatter-add accumulator
__device__ int   g_idx_is64;                 // 1 if src/dst are int64, else int32

// ---------------------------------------------------------------------------
// Kernel 0: detect index dtype (graph-safe, deterministic).
// If arrays are int64 with values in [0, 50000), every odd 32-bit word is 0.
// Probability that 128 genuine int32 indices are all zero: ~(1/50000)^128 = 0.
// ---------------------------------------------------------------------------
__global__ void detect_idx_kernel(const unsigned int* __restrict__ src_w,
                                  const unsigned int* __restrict__ dst_w) {
    if (threadIdx.x == 0 && blockIdx.x == 0) {
        unsigned int acc = 0;
        // Inspect first 64 odd words of each array (all within int32-sized buffer).
#pragma unroll 8
        for (int i = 0; i < 64; i++) {
            acc |= src_w[2 * i + 1];
            acc |= dst_w[2 * i + 1];
        }
        g_idx_is64 = (acc == 0u) ? 1 : 0;
    }
}

// ---------------------------------------------------------------------------
// Kernel 1: zero g_agg
// ---------------------------------------------------------------------------
__global__ void zero_agg_kernel() {
    size_t i = (size_t)blockIdx.x * blockDim.x + threadIdx.x;
    size_t n4 = (size_t)ROWS_ * D_ / 4;
    float4 z = make_float4(0.f, 0.f, 0.f, 0.f);
    if (i < n4) ((float4*)g_agg)[i] = z;
}

// ---------------------------------------------------------------------------
// Kernel 2: SGEMM  M[r,:] = H[r,:] @ W,  (ROWS x 128) @ (128 x 128)
// Block tile 128 rows x 128 cols, full K=128, 256 threads, 8x8 per thread.
// Dynamic smem: As[128][128] + Bs[128][128] = 128 KB.
// ---------------------------------------------------------------------------
__global__ __launch_bounds__(256, 1)
void gemm_kernel(const float* __restrict__ Hm, const float* __restrict__ W) {
    extern __shared__ float sm[];
    float* As = sm;              // [128][128] row-major (row, k)
    float* Bs = sm + 128 * 128;  // [128][128] row-major (k, col)

    const int tid  = threadIdx.x;
    const int row0 = blockIdx.x * 128;

    // Load W (16384 floats): 256 threads * 16 float4
#pragma unroll
    for (int i = 0; i < 16; i++) {
        int fi = (i * 256 + tid) * 4;
        *(float4*)&Bs[fi] = *(const float4*)&W[fi];
    }
    // Load H tile (128 rows x 128): 4096 float4
#pragma unroll
    for (int i = 0; i < 16; i++) {
        int idx4 = i * 256 + tid;       // float4 index 0..4095
        int r = idx4 >> 5;              // 32 float4 per row
        int c = (idx4 & 31) * 4;
        float4 v = make_float4(0.f, 0.f, 0.f, 0.f);
        int gr = row0 + r;
        if (gr < ROWS_) v = *(const float4*)&Hm[(size_t)gr * D_ + c];
        *(float4*)&As[r * D_ + c] = v;
    }
    __syncthreads();

    const int tx = tid & 15;   // 16 col-groups of 8
    const int ty = tid >> 4;   // 16 row-groups of 8

    float acc[8][8];
#pragma unroll
    for (int i = 0; i < 8; i++)
#pragma unroll
        for (int j = 0; j < 8; j++) acc[i][j] = 0.f;

#pragma unroll 8
    for (int k = 0; k < 128; k++) {
        float a[8], b[8];
#pragma unroll
        for (int i = 0; i < 8; i++) a[i] = As[(ty * 8 + i) * D_ + k];  // broadcast reads
        *(float4*)&b[0] = *(float4*)&Bs[k * 128 + tx * 8];
        *(float4*)&b[4] = *(float4*)&Bs[k * 128 + tx * 8 + 4];
#pragma unroll
        for (int i = 0; i < 8; i++)
#pragma unroll
            for (int j = 0; j < 8; j++) acc[i][j] += a[i] * b[j];
    }

#pragma unroll
    for (int i = 0; i < 8; i++) {
        int gr = row0 + ty * 8 + i;
        if (gr < ROWS_) {
            float* out = g_m + (size_t)gr * D_ + tx * 8;
            *(float4*)&out[0] = *(float4*)&acc[i][0];
            *(float4*)&out[4] = *(float4*)&acc[i][4];
        }
    }
}

// ---------------------------------------------------------------------------
// Kernel 3: edge scatter-add  agg[b, dst[e], :] += m[b, src[e], :]
// One warp per edge; lane l handles float4 chunk l of D=128.
// Vectorized no-return reduction: red.global.add.v4.f32 (sm_90+).
// ---------------------------------------------------------------------------
__device__ __forceinline__ void red_add_v4(float* p, float4 v) {
    asm volatile("red.global.add.v4.f32 [%0], {%1, %2, %3, %4};"
                 :: "l"(p), "f"(v.x), "f"(v.y), "f"(v.z), "f"(v.w)
                 : "memory");
}

__device__ __forceinline__ int load_idx(const void* p, int e, int is64) {
    if (is64) return (int)((const long long*)p)[e];
    return ((const int*)p)[e];
}

__global__ __launch_bounds__(256)
void scatter_kernel(const void* __restrict__ src,
                    const void* __restrict__ dst) {
    int warp = (blockIdx.x * blockDim.x + threadIdx.x) >> 5;
    int lane = threadIdx.x & 31;
    if (warp >= E_) return;

    const int is64 = g_idx_is64;
    int s = load_idx(src, warp, is64);
    int d = load_idx(dst, warp, is64);

    // batch 0
    {
        float4 v = *(const float4*)(g_m + (size_t)s * D_ + lane * 4);
        red_add_v4(g_agg + (size_t)d * D_ + lane * 4, v);
    }
    // batch 1
    {
        float4 v = *(const float4*)(g_m + (size_t)(N_ + s) * D_ + lane * 4);
        red_add_v4(g_agg + (size_t)(N_ + d) * D_ + lane * 4, v);
    }
}

// ---------------------------------------------------------------------------
// Kernel 4: out = LayerNorm(H + gelu_exact(agg)) * gamma + beta
// One warp per row (128 floats -> 1 float4 per lane).
// ---------------------------------------------------------------------------
__device__ __forceinline__ float gelu_exact(float v) {
    return 0.5f * v * (1.0f + erff(v * 0.70710678118654752f));
}

__device__ __forceinline__ float warp_sum(float s) {
#pragma unroll
    for (int o = 16; o > 0; o >>= 1) s += __shfl_xor_sync(0xffffffffu, s, o);
    return s;
}

__global__ __launch_bounds__(256)
void fuse_ln_kernel(const float* __restrict__ Hm,
                    const float* __restrict__ gamma,
                    const float* __restrict__ beta,
                    float* __restrict__ out) {
    int row  = (blockIdx.x * blockDim.x + threadIdx.x) >> 5;
    int lane = threadIdx.x & 31;
    if (row >= ROWS_) return;

    float4 h = *(const float4*)(Hm    + (size_t)row * D_ + lane * 4);
    float4 a = *(const float4*)(g_agg + (size_t)row * D_ + lane * 4);

    float x0 = h.x + gelu_exact(a.x);
    float x1 = h.y + gelu_exact(a.y);
    float x2 = h.z + gelu_exact(a.z);
    float x3 = h.w + gelu_exact(a.w);

    float mean = warp_sum(x0 + x1 + x2 + x3) * (1.0f / D_);

    float d0 = x0 - mean, d1 = x1 - mean, d2 = x2 - mean, d3 = x3 - mean;
    float var = warp_sum(d0 * d0 + d1 * d1 + d2 * d2 + d3 * d3) * (1.0f / D_);
    float inv = rsqrtf(var + 1e-5f);

    float4 g = *(const float4*)(gamma + lane * 4);
    float4 b = *(const float4*)(beta  + lane * 4);

    float4 o;
    o.x = d0 * inv * g.x + b.x;
    o.y = d1 * inv * g.y + b.y;
    o.z = d2 * inv * g.z + b.z;
    o.w = d3 * inv * g.w + b.w;
    *(float4*)(out + (size_t)row * D_ + lane * 4) = o;
}

// ---------------------------------------------------------------------------
// Launcher
// ---------------------------------------------------------------------------
extern "C" void kernel_launch(void* const* d_in, const int* in_sizes, int n_in,
                              void* d_out, int out_size) {
    const float* H     = (const float*)d_in[0];
    const void*  src   = d_in[1];
    const void*  dst   = d_in[2];
    const float* W     = (const float*)d_in[3];
    const float* gamma = (const float*)d_in[4];
    const float* beta  = (const float*)d_in[5];
    float*       out   = (float*)d_out;

    (void)in_sizes; (void)n_in; (void)out_size;

    // Opt in to 128 KB dynamic smem for the GEMM (idempotent, host-side config).
    cudaFuncSetAttribute(gemm_kernel,
                         cudaFuncAttributeMaxDynamicSharedMemorySize,
                         128 * 1024);

    // 0) index dtype probe
    detect_idx_kernel<<<1, 32>>>((const unsigned int*)src,
                                 (const unsigned int*)dst);
    // 1) zero accumulator
    {
        size_t n4 = (size_t)ROWS_ * D_ / 4;
        int blocks = (int)((n4 + 255) / 256);
        zero_agg_kernel<<<blocks, 256>>>();
    }
    // 2) GEMM m = H @ W
    {
        int blocks = (ROWS_ + 127) / 128;  // 782
        gemm_kernel<<<blocks, 256, 128 * 1024>>>(H, W);
    }
    // 3) edge scatter-add (8 warps = 8 edges per block)
    {
        int blocks = (E_ * 32 + 255) / 256;  // 100000
        scatter_kernel<<<blocks, 256>>>(src, dst);
    }
    // 4) fused gelu + layernorm
    {
        int blocks = (ROWS_ * 32 + 255) / 256;  // 12500
        fuse_ln_kernel<<<blocks, 256>>>(H, gamma, beta, out);
    }
}

// round 5
// speedup vs baseline: 1.0930x; 1.0930x over previous
#include <cuda_runtime.h>
#include <cuda_bf16.h>
#include <math.h>

// Problem shape (fixed by dataset)
#define B_    2
#define N_    50000
#define D_    128
#define E_    800000
#define ROWS_ (B_ * N_)   // 100000 rows when H viewed as [B*N, D]

// Scratch: device globals (no allocation allowed)
__device__ float g_m[(size_t)ROWS_ * D_];   // m = H @ W
__device__ int   g_idx_is64;                // 1 if src/dst are int64, else int32
__device__ int   g_count[N_];               // in-degree histogram
__device__ int   g_offset[N_ + 1];          // CSR offsets
__device__ int   g_cursor[N_];              // fill cursors
__device__ int   g_esrc[E_];                // edge src ids grouped by dst

// ---------------------------------------------------------------------------
// Kernel 0: detect index dtype (graph-safe, deterministic).
// int64 indices < 50000 have zero odd 32-bit words; 128 genuine random int32
// indices all being zero has probability ~(1/50000)^128.
// ---------------------------------------------------------------------------
__global__ void detect_idx_kernel(const unsigned int* __restrict__ src_w,
                                  const unsigned int* __restrict__ dst_w) {
    if (threadIdx.x == 0 && blockIdx.x == 0) {
        unsigned int acc = 0;
#pragma unroll 8
        for (int i = 0; i < 64; i++) {
            acc |= src_w[2 * i + 1];
            acc |= dst_w[2 * i + 1];
        }
        g_idx_is64 = (acc == 0u) ? 1 : 0;
    }
}

__device__ __forceinline__ int load_idx(const void* p, int e, int is64) {
    if (is64) return (int)((const long long*)p)[e];
    return ((const int*)p)[e];
}

// ---------------------------------------------------------------------------
// Kernel 1: zero the histogram
// ---------------------------------------------------------------------------
__global__ void zero_count_kernel() {
    int i = blockIdx.x * blockDim.x + threadIdx.x;
    if (i < N_) g_count[i] = 0;
}

// ---------------------------------------------------------------------------
// Kernel 2: in-degree histogram over dst
// ---------------------------------------------------------------------------
__global__ void hist_kernel(const void* __restrict__ dst) {
    int e = blockIdx.x * blockDim.x + threadIdx.x;
    if (e < E_) {
        int d = load_idx(dst, e, g_idx_is64);
        atomicAdd(&g_count[d], 1);
    }
}

// ---------------------------------------------------------------------------
// Kernel 3: single-block exclusive scan over g_count -> g_offset, g_cursor
// 1024 threads, each handles a contiguous chunk of ceil(N/1024) entries.
// ---------------------------------------------------------------------------
__global__ __launch_bounds__(1024)
void scan_kernel() {
    __shared__ int sh[1024];
    const int tid = threadIdx.x;
    const int per = (N_ + 1023) / 1024;  // 49
    const int base = tid * per;

    int s = 0;
    for (int i = 0; i < per; i++) {
        int j = base + i;
        if (j < N_) s += g_count[j];
    }
    sh[tid] = s;
    __syncthreads();

    // Hillis-Steele inclusive scan over 1024 partials
    for (int o = 1; o < 1024; o <<= 1) {
        int t = (tid >= o) ? sh[tid - o] : 0;
        __syncthreads();
        sh[tid] += t;
        __syncthreads();
    }
    int run = sh[tid] - s;  // exclusive prefix for this chunk

    for (int i = 0; i < per; i++) {
        int j = base + i;
        if (j < N_) {
            g_offset[j] = run;
            g_cursor[j] = run;
            run += g_count[j];
        }
    }
    if (tid == 1023) g_offset[N_] = E_;
}

// ---------------------------------------------------------------------------
// Kernel 4: bucket edges by dst:  g_esrc[cursor[d]++] = src[e]
// ---------------------------------------------------------------------------
__global__ void fill_kernel(const void* __restrict__ src,
                            const void* __restrict__ dst) {
    int e = blockIdx.x * blockDim.x + threadIdx.x;
    if (e < E_) {
        const int is64 = g_idx_is64;
        int s = load_idx(src, e, is64);
        int d = load_idx(dst, e, is64);
        int pos = atomicAdd(&g_cursor[d], 1);
        g_esrc[pos] = s;
    }
}

// ---------------------------------------------------------------------------
// Kernel 5: SGEMM  m[r,:] = H[r,:] @ W, with packed f32x2 FMAs (FFMA2).
// Block tile 128x128, full K=128, 256 threads, 8x8 per thread (as 8x4 f32x2).
// Dynamic smem: As[128][128] + Bs[128][128] = 128 KB.
// ---------------------------------------------------------------------------
__device__ __forceinline__ unsigned long long pack2(float v) {
    unsigned long long r;
    unsigned int u = __float_as_uint(v);
    asm("mov.b64 %0, {%1, %1};" : "=l"(r) : "r"(u));
    return r;
}
#define FMA2(d, a, b, c) \
    asm("fma.rn.f32x2 %0, %1, %2, %3;" : "=l"(d) : "l"(a), "l"(b), "l"(c))

__global__ __launch_bounds__(256, 1)
void gemm_kernel(const float* __restrict__ Hm, const float* __restrict__ W) {
    extern __shared__ float sm[];
    float* As = sm;              // [128][128] (row, k)
    float* Bs = sm + 128 * 128;  // [128][128] (k, col)

    const int tid  = threadIdx.x;
    const int row0 = blockIdx.x * 128;

    // Load W: 16384 floats = 4096 float4
#pragma unroll
    for (int i = 0; i < 16; i++) {
        int fi = (i * 256 + tid) * 4;
        *(float4*)&Bs[fi] = *(const float4*)&W[fi];
    }
    // Load H tile (128 rows x 128)
#pragma unroll
    for (int i = 0; i < 16; i++) {
        int idx4 = i * 256 + tid;
        int r = idx4 >> 5;
        int c = (idx4 & 31) * 4;
        float4 v = make_float4(0.f, 0.f, 0.f, 0.f);
        int gr = row0 + r;
        if (gr < ROWS_) v = *(const float4*)&Hm[(size_t)gr * D_ + c];
        *(float4*)&As[r * D_ + c] = v;
    }
    __syncthreads();

    const int tx = tid & 15;   // 16 col-groups of 8
    const int ty = tid >> 4;   // 16 row-groups of 8

    unsigned long long acc[8][4];  // 8 rows x 4 col-pairs
#pragma unroll
    for (int i = 0; i < 8; i++)
#pragma unroll
        for (int j = 0; j < 4; j++) acc[i][j] = 0ull;

#pragma unroll 4
    for (int k = 0; k < 128; k++) {
        unsigned long long bp[4];
        *(ulonglong2*)&bp[0] = *(ulonglong2*)&Bs[k * 128 + tx * 8];
        *(ulonglong2*)&bp[2] = *(ulonglong2*)&Bs[k * 128 + tx * 8 + 4];
        unsigned long long ap[8];
#pragma unroll
        for (int i = 0; i < 8; i++) ap[i] = pack2(As[(ty * 8 + i) * D_ + k]);
#pragma unroll
        for (int i = 0; i < 8; i++)
#pragma unroll
            for (int j = 0; j < 4; j++) FMA2(acc[i][j], ap[i], bp[j], acc[i][j]);
    }

#pragma unroll
    for (int i = 0; i < 8; i++) {
        int gr = row0 + ty * 8 + i;
        if (gr < ROWS_) {
            float* out = g_m + (size_t)gr * D_ + tx * 8;
            *(ulonglong2*)&out[0] = make_ulonglong2(acc[i][0], acc[i][1]);
            *(ulonglong2*)&out[4] = make_ulonglong2(acc[i][2], acc[i][3]);
        }
    }
}

// ---------------------------------------------------------------------------
// Kernel 6: fused gather-accumulate + gelu + residual + LayerNorm.
// One warp per dst node, covering BOTH batches (rows d and N_+d).
// Lane l owns float4 chunk l of D=128.
// ---------------------------------------------------------------------------
__device__ __forceinline__ float gelu_exact(float v) {
    return 0.5f * v * (1.0f + erff(v * 0.70710678118654752f));
}

__device__ __forceinline__ float warp_sum(float s) {
#pragma unroll
    for (int o = 16; o > 0; o >>= 1) s += __shfl_xor_sync(0xffffffffu, s, o);
    return s;
}

__device__ __forceinline__ void ln_row(const float* __restrict__ Hrow,
                                       float4 a, float4 g, float4 b,
                                       float* __restrict__ outrow, int lane) {
    float4 h = *(const float4*)(Hrow + lane * 4);
    float x0 = h.x + gelu_exact(a.x);
    float x1 = h.y + gelu_exact(a.y);
    float x2 = h.z + gelu_exact(a.z);
    float x3 = h.w + gelu_exact(a.w);

    float mean = warp_sum(x0 + x1 + x2 + x3) * (1.0f / D_);
    float d0 = x0 - mean, d1 = x1 - mean, d2 = x2 - mean, d3 = x3 - mean;
    float var = warp_sum(d0 * d0 + d1 * d1 + d2 * d2 + d3 * d3) * (1.0f / D_);
    float inv = rsqrtf(var + 1e-5f);

    float4 o;
    o.x = d0 * inv * g.x + b.x;
    o.y = d1 * inv * g.y + b.y;
    o.z = d2 * inv * g.z + b.z;
    o.w = d3 * inv * g.w + b.w;
    *(float4*)(outrow + lane * 4) = o;
}

__global__ __launch_bounds__(256)
void gather_ln_kernel(const float* __restrict__ Hm,
                      const float* __restrict__ gamma,
                      const float* __restrict__ beta,
                      float* __restrict__ out) {
    const int node = (blockIdx.x * blockDim.x + threadIdx.x) >> 5;
    const int lane = threadIdx.x & 31;
    if (node >= N_) return;

    const int beg = g_offset[node];
    const int end = g_offset[node + 1];

    float4 acc0 = make_float4(0.f, 0.f, 0.f, 0.f);
    float4 acc1 = make_float4(0.f, 0.f, 0.f, 0.f);

    for (int base = beg; base < end; base += 32) {
        int k = base + lane;
        int myS = (k < end) ? g_esrc[k] : 0;
        int cnt = min(32, end - base);
        for (int j = 0; j < cnt; j++) {
            int s = __shfl_sync(0xffffffffu, myS, j);
            const float* p0 = g_m + (size_t)s * D_ + lane * 4;
            const float* p1 = g_m + (size_t)(N_ + s) * D_ + lane * 4;
            float4 v0 = *(const float4*)p0;
            float4 v1 = *(const float4*)p1;
            acc0.x += v0.x; acc0.y += v0.y; acc0.z += v0.z; acc0.w += v0.w;
            acc1.x += v1.x; acc1.y += v1.y; acc1.z += v1.z; acc1.w += v1.w;
        }
    }

    float4 g = *(const float4*)(gamma + lane * 4);
    float4 b = *(const float4*)(beta  + lane * 4);

    ln_row(Hm + (size_t)node * D_,        acc0, g, b,
           out + (size_t)node * D_,        lane);
    ln_row(Hm + (size_t)(N_ + node) * D_, acc1, g, b,
           out + (size_t)(N_ + node) * D_, lane);
}

// ---------------------------------------------------------------------------
// Launcher
// ---------------------------------------------------------------------------
extern "C" void kernel_launch(void* const* d_in, const int* in_sizes, int n_in,
                              void* d_out, int out_size) {
    const float* H     = (const float*)d_in[0];
    const void*  src   = d_in[1];
    const void*  dst   = d_in[2];
    const float* W     = (const float*)d_in[3];
    const float* gamma = (const float*)d_in[4];
    const float* beta  = (const float*)d_in[5];
    float*       out   = (float*)d_out;

    (void)in_sizes; (void)n_in; (void)out_size;

    cudaFuncSetAttribute(gemm_kernel,
                         cudaFuncAttributeMaxDynamicSharedMemorySize,
                         128 * 1024);

    // 0) index dtype probe
    detect_idx_kernel<<<1, 32>>>((const unsigned int*)src,
                                 (const unsigned int*)dst);
    // 1) CSR build: zero counts -> histogram -> scan -> fill
    zero_count_kernel<<<(N_ + 255) / 256, 256>>>();
    // 2) GEMM m = H @ W (independent of CSR build, FFMA2 inner loop)
    gemm_kernel<<<(ROWS_ + 127) / 128, 256, 128 * 1024>>>(H, W);
    hist_kernel<<<(E_ + 255) / 256, 256>>>(dst);
    scan_kernel<<<1, 1024>>>();
    fill_kernel<<<(E_ + 255) / 256, 256>>>(src, dst);
    // 3) fused gather + gelu + residual + LayerNorm (warp per node, both batches)
    gather_ln_kernel<<<(N_ * 32 + 255) / 256, 256>>>(H, gamma, beta, out);
}

// round 6
// speedup vs baseline: 1.2272x; 1.1228x over previous
#include <cuda_runtime.h>
#include <cuda_fp16.h>
#include <math.h>

// Problem shape (fixed by dataset)
#define B_    2
#define N_    50000
#define D_    128
#define E_    800000
#define ROWS_ (B_ * N_)   // 100000 rows when H viewed as [B*N, D]

// Scratch: device globals (no allocation allowed)
// m stored fp16, node-interleaved: g_mh[node*256 + batch*128 + d]
__device__ __half g_mh[(size_t)N_ * 256];
__device__ int    g_idx_is64;               // 1 if src/dst are int64, else int32
__device__ int    g_count[N_];              // in-degree histogram
__device__ int    g_offset[N_ + 1];         // CSR offsets
__device__ int    g_cursor[N_];             // fill cursors
__device__ int    g_esrc[E_];               // edge src ids grouped by dst

// ---------------------------------------------------------------------------
// Kernel 0: detect index dtype (graph-safe, deterministic).
// int64 indices < 50000 have zero odd 32-bit words; 128 genuine random int32
// indices all being zero has probability ~(1/50000)^128.
// ---------------------------------------------------------------------------
__global__ void detect_idx_kernel(const unsigned int* __restrict__ src_w,
                                  const unsigned int* __restrict__ dst_w) {
    if (threadIdx.x == 0 && blockIdx.x == 0) {
        unsigned int acc = 0;
#pragma unroll 8
        for (int i = 0; i < 64; i++) {
            acc |= src_w[2 * i + 1];
            acc |= dst_w[2 * i + 1];
        }
        g_idx_is64 = (acc == 0u) ? 1 : 0;
    }
}

// ---------------------------------------------------------------------------
// Kernel 1: zero the histogram
// ---------------------------------------------------------------------------
__global__ void zero_count_kernel() {
    int i = blockIdx.x * blockDim.x + threadIdx.x;
    if (i < N_) g_count[i] = 0;
}

// ---------------------------------------------------------------------------
// Kernel 2: in-degree histogram over dst (4 edges/thread, vector loads)
// E_ = 800000 is divisible by 4.
// ---------------------------------------------------------------------------
__global__ void hist_kernel(const void* __restrict__ dst) {
    int i = blockIdx.x * blockDim.x + threadIdx.x;
    if (i * 4 >= E_) return;
    int d0, d1, d2, d3;
    if (g_idx_is64) {
        longlong2 a = ((const longlong2*)dst)[i * 2];
        longlong2 b = ((const longlong2*)dst)[i * 2 + 1];
        d0 = (int)a.x; d1 = (int)a.y; d2 = (int)b.x; d3 = (int)b.y;
    } else {
        int4 v = ((const int4*)dst)[i];
        d0 = v.x; d1 = v.y; d2 = v.z; d3 = v.w;
    }
    atomicAdd(&g_count[d0], 1);
    atomicAdd(&g_count[d1], 1);
    atomicAdd(&g_count[d2], 1);
    atomicAdd(&g_count[d3], 1);
}

// ---------------------------------------------------------------------------
// Kernel 3: single-block exclusive scan over g_count -> g_offset, g_cursor
// ---------------------------------------------------------------------------
__global__ __launch_bounds__(1024)
void scan_kernel() {
    __shared__ int sh[1024];
    const int tid = threadIdx.x;
    const int per = (N_ + 1023) / 1024;  // 49
    const int base = tid * per;

    int s = 0;
    for (int i = 0; i < per; i++) {
        int j = base + i;
        if (j < N_) s += g_count[j];
    }
    sh[tid] = s;
    __syncthreads();

    for (int o = 1; o < 1024; o <<= 1) {
        int t = (tid >= o) ? sh[tid - o] : 0;
        __syncthreads();
        sh[tid] += t;
        __syncthreads();
    }
    int run = sh[tid] - s;  // exclusive prefix for this chunk

    for (int i = 0; i < per; i++) {
        int j = base + i;
        if (j < N_) {
            g_offset[j] = run;
            g_cursor[j] = run;
            run += g_count[j];
        }
    }
    if (tid == 1023) g_offset[N_] = E_;
}

// ---------------------------------------------------------------------------
// Kernel 4: bucket edges by dst (4 edges/thread):  g_esrc[cursor[d]++] = src[e]
// ---------------------------------------------------------------------------
__global__ void fill_kernel(const void* __restrict__ src,
                            const void* __restrict__ dst) {
    int i = blockIdx.x * blockDim.x + threadIdx.x;
    if (i * 4 >= E_) return;
    int s0, s1, s2, s3, d0, d1, d2, d3;
    if (g_idx_is64) {
        longlong2 sa = ((const longlong2*)src)[i * 2];
        longlong2 sb = ((const longlong2*)src)[i * 2 + 1];
        longlong2 da = ((const longlong2*)dst)[i * 2];
        longlong2 db = ((const longlong2*)dst)[i * 2 + 1];
        s0 = (int)sa.x; s1 = (int)sa.y; s2 = (int)sb.x; s3 = (int)sb.y;
        d0 = (int)da.x; d1 = (int)da.y; d2 = (int)db.x; d3 = (int)db.y;
    } else {
        int4 sv = ((const int4*)src)[i];
        int4 dv = ((const int4*)dst)[i];
        s0 = sv.x; s1 = sv.y; s2 = sv.z; s3 = sv.w;
        d0 = dv.x; d1 = dv.y; d2 = dv.z; d3 = dv.w;
    }
    g_esrc[atomicAdd(&g_cursor[d0], 1)] = s0;
    g_esrc[atomicAdd(&g_cursor[d1], 1)] = s1;
    g_esrc[atomicAdd(&g_cursor[d2], 1)] = s2;
    g_esrc[atomicAdd(&g_cursor[d3], 1)] = s3;
}

// ---------------------------------------------------------------------------
// Kernel 5: SGEMM  m[r,:] = H[r,:] @ W, packed f32x2 FMAs, fp16 output
// into node-interleaved layout. Block tile 128x128, 256 threads, 8x8/thread.
// ---------------------------------------------------------------------------
__device__ __forceinline__ unsigned long long pack2(float v) {
    unsigned long long r;
    unsigned int u = __float_as_uint(v);
    asm("mov.b64 %0, {%1, %1};" : "=l"(r) : "r"(u));
    return r;
}
#define FMA2(d, a, b, c) \
    asm("fma.rn.f32x2 %0, %1, %2, %3;" : "=l"(d) : "l"(a), "l"(b), "l"(c))

__global__ __launch_bounds__(256, 1)
void gemm_kernel(const float* __restrict__ Hm, const float* __restrict__ W) {
    extern __shared__ float sm[];
    float* As = sm;              // [128][128] (row, k)
    float* Bs = sm + 128 * 128;  // [128][128] (k, col)

    const int tid  = threadIdx.x;
    const int row0 = blockIdx.x * 128;

#pragma unroll
    for (int i = 0; i < 16; i++) {
        int fi = (i * 256 + tid) * 4;
        *(float4*)&Bs[fi] = *(const float4*)&W[fi];
    }
#pragma unroll
    for (int i = 0; i < 16; i++) {
        int idx4 = i * 256 + tid;
        int r = idx4 >> 5;
        int c = (idx4 & 31) * 4;
        float4 v = make_float4(0.f, 0.f, 0.f, 0.f);
        int gr = row0 + r;
        if (gr < ROWS_) v = *(const float4*)&Hm[(size_t)gr * D_ + c];
        *(float4*)&As[r * D_ + c] = v;
    }
    __syncthreads();

    const int tx = tid & 15;   // 16 col-groups of 8
    const int ty = tid >> 4;   // 16 row-groups of 8

    unsigned long long acc[8][4];
#pragma unroll
    for (int i = 0; i < 8; i++)
#pragma unroll
        for (int j = 0; j < 4; j++) acc[i][j] = 0ull;

#pragma unroll 4
    for (int k = 0; k < 128; k++) {
        unsigned long long bp[4];
        *(ulonglong2*)&bp[0] = *(ulonglong2*)&Bs[k * 128 + tx * 8];
        *(ulonglong2*)&bp[2] = *(ulonglong2*)&Bs[k * 128 + tx * 8 + 4];
        unsigned long long ap[8];
#pragma unroll
        for (int i = 0; i < 8; i++) ap[i] = pack2(As[(ty * 8 + i) * D_ + k]);
#pragma unroll
        for (int i = 0; i < 8; i++)
#pragma unroll
            for (int j = 0; j < 4; j++) FMA2(acc[i][j], ap[i], bp[j], acc[i][j]);
    }

#pragma unroll
    for (int i = 0; i < 8; i++) {
        int gr = row0 + ty * 8 + i;
        if (gr < ROWS_) {
            int b = (gr >= N_) ? 1 : 0;
            int n = gr - b * N_;
            // convert 8 fp32 (4 f32x2 pairs) -> 8 fp16 -> one uint4 store
            __half2 h0 = __float22half2_rn(*(float2*)&acc[i][0]);
            __half2 h1 = __float22half2_rn(*(float2*)&acc[i][1]);
            __half2 h2 = __float22half2_rn(*(float2*)&acc[i][2]);
            __half2 h3 = __float22half2_rn(*(float2*)&acc[i][3]);
            uint4 v;
            v.x = *(unsigned int*)&h0;
            v.y = *(unsigned int*)&h1;
            v.z = *(unsigned int*)&h2;
            v.w = *(unsigned int*)&h3;
            *(uint4*)(g_mh + (size_t)n * 256 + b * 128 + tx * 8) = v;
        }
    }
}

// ---------------------------------------------------------------------------
// Kernel 6: fused gather-accumulate + gelu + residual + LayerNorm.
// One warp per dst node. Per edge: one contiguous 512B read (both batches).
// Lanes 0-15 own batch 0 (8 features each), lanes 16-31 own batch 1.
// ---------------------------------------------------------------------------
__device__ __forceinline__ float gelu_exact(float v) {
    return 0.5f * v * (1.0f + erff(v * 0.70710678118654752f));
}

// reduce across the 16-lane half-group (xor offsets < 16 stay in-group)
__device__ __forceinline__ float half_sum(float s) {
#pragma unroll
    for (int o = 8; o > 0; o >>= 1) s += __shfl_xor_sync(0xffffffffu, s, o);
    return s;
}

__global__ __launch_bounds__(256)
void gather_ln_kernel(const float* __restrict__ Hm,
                      const float* __restrict__ gamma,
                      const float* __restrict__ beta,
                      float* __restrict__ out) {
    const int node = (blockIdx.x * blockDim.x + threadIdx.x) >> 5;
    const int lane = threadIdx.x & 31;
    if (node >= N_) return;

    const int beg = g_offset[node];
    const int end = g_offset[node + 1];

    float a0 = 0.f, a1 = 0.f, a2 = 0.f, a3 = 0.f;
    float a4 = 0.f, a5 = 0.f, a6 = 0.f, a7 = 0.f;

    for (int base = beg; base < end; base += 32) {
        int k = base + lane;
        int myS = (k < end) ? g_esrc[k] : 0;
        int cnt = min(32, end - base);
#pragma unroll 4
        for (int j = 0; j < cnt; j++) {
            int s = __shfl_sync(0xffffffffu, myS, j);
            // lane*8 halves into the 256-half node record (batch-interleaved)
            uint4 v = *(const uint4*)(g_mh + (size_t)s * 256 + lane * 8);
            float2 f0 = __half22float2(*(__half2*)&v.x);
            float2 f1 = __half22float2(*(__half2*)&v.y);
            float2 f2 = __half22float2(*(__half2*)&v.z);
            float2 f3 = __half22float2(*(__half2*)&v.w);
            a0 += f0.x; a1 += f0.y; a2 += f1.x; a3 += f1.y;
            a4 += f2.x; a5 += f2.y; a6 += f3.x; a7 += f3.y;
        }
    }

    // lane -> (batch, feature group)
    const int bsel = lane >> 4;          // 0 or 1
    const int fg   = lane & 15;          // 16 groups of 8 features
    const size_t rowoff = (size_t)(bsel * N_ + node) * D_ + fg * 8;

    float4 h0 = *(const float4*)(Hm + rowoff);
    float4 h1 = *(const float4*)(Hm + rowoff + 4);

    float x0 = h0.x + gelu_exact(a0);
    float x1 = h0.y + gelu_exact(a1);
    float x2 = h0.z + gelu_exact(a2);
    float x3 = h0.w + gelu_exact(a3);
    float x4 = h1.x + gelu_exact(a4);
    float x5 = h1.y + gelu_exact(a5);
    float x6 = h1.z + gelu_exact(a6);
    float x7 = h1.w + gelu_exact(a7);

    float mean = half_sum(x0 + x1 + x2 + x3 + x4 + x5 + x6 + x7) * (1.0f / D_);

    float d0 = x0 - mean, d1 = x1 - mean, d2 = x2 - mean, d3 = x3 - mean;
    float d4 = x4 - mean, d5 = x5 - mean, d6 = x6 - mean, d7 = x7 - mean;
    float var = half_sum(d0 * d0 + d1 * d1 + d2 * d2 + d3 * d3 +
                         d4 * d4 + d5 * d5 + d6 * d6 + d7 * d7) * (1.0f / D_);
    float inv = rsqrtf(var + 1e-5f);

    float4 g0 = *(const float4*)(gamma + fg * 8);
    float4 g1 = *(const float4*)(gamma + fg * 8 + 4);
    float4 b0 = *(const float4*)(beta + fg * 8);
    float4 b1 = *(const float4*)(beta + fg * 8 + 4);

    float4 o0, o1;
    o0.x = d0 * inv * g0.x + b0.x;
    o0.y = d1 * inv * g0.y + b0.y;
    o0.z = d2 * inv * g0.z + b0.z;
    o0.w = d3 * inv * g0.w + b0.w;
    o1.x = d4 * inv * g1.x + b1.x;
    o1.y = d5 * inv * g1.y + b1.y;
    o1.z = d6 * inv * g1.z + b1.z;
    o1.w = d7 * inv * g1.w + b1.w;
    *(float4*)(out + rowoff)     = o0;
    *(float4*)(out + rowoff + 4) = o1;
}

// ---------------------------------------------------------------------------
// Launcher
// ---------------------------------------------------------------------------
extern "C" void kernel_launch(void* const* d_in, const int* in_sizes, int n_in,
                              void* d_out, int out_size) {
    const float* H     = (const float*)d_in[0];
    const void*  src   = d_in[1];
    const void*  dst   = d_in[2];
    const float* W     = (const float*)d_in[3];
    const float* gamma = (const float*)d_in[4];
    const float* beta  = (const float*)d_in[5];
    float*       out   = (float*)d_out;

    (void)in_sizes; (void)n_in; (void)out_size;

    cudaFuncSetAttribute(gemm_kernel,
                         cudaFuncAttributeMaxDynamicSharedMemorySize,
                         128 * 1024);

    // 0) index dtype probe
    detect_idx_kernel<<<1, 32>>>((const unsigned int*)src,
                                 (const unsigned int*)dst);
    // 1) CSR build (vectorized)
    zero_count_kernel<<<(N_ + 255) / 256, 256>>>();
    gemm_kernel<<<(ROWS_ + 127) / 128, 256, 128 * 1024>>>(H, W);
    hist_kernel<<<(E_ / 4 + 255) / 256, 256>>>(dst);
    scan_kernel<<<1, 1024>>>();
    fill_kernel<<<(E_ / 4 + 255) / 256, 256>>>(src, dst);
    // 2) fused gather + gelu + residual + LayerNorm
    gather_ln_kernel<<<(N_ * 32 + 255) / 256, 256>>>(H, gamma, beta, out);
}